// round 2
// baseline (speedup 1.0000x reference)
#include <cuda_runtime.h>
#include <math.h>

// Problem constants
#define BATCH 2
#define TSEQ  2048
#define CDIM  1024
#define NH    16
#define HD    64
#define M_ROWS (BATCH*TSEQ)      // 4096
#define N_QKV  (3*CDIM)          // 3072

// Scratch (no cudaMalloc allowed): Q,K,V in (b,h,t,d) layout; attn out in (b,t,c)
__device__ float g_Q[BATCH*NH*TSEQ*HD];
__device__ float g_K[BATCH*NH*TSEQ*HD];
__device__ float g_V[BATCH*NH*TSEQ*HD];
__device__ float g_AO[BATCH*TSEQ*CDIM];

// ---------------------------------------------------------------------------
// Classic SGEMM: Out[m,n] = sum_k A[m,k]*W[n,k] + bias[n]
// BM=128, BN=128, BK=16, 8x8 micro-tile, 256 threads.
// EPI=0: scatter into g_Q/g_V/g_K per einops (d,kk,h) factorization of n.
// EPI=1: A is g_AO (device symbol), plain store to Out.
// ---------------------------------------------------------------------------
#define GBM 128
#define GBN 128
#define GBK 16

template<int EPI>
__global__ __launch_bounds__(256)
void sgemm_kernel(const float* __restrict__ A, const float* __restrict__ W,
                  const float* __restrict__ bias, float* __restrict__ Out,
                  int M, int N, int K)
{
    __shared__ __align__(16) float As[GBK][GBM];
    __shared__ __align__(16) float Bs[GBK][GBN];

    const float* Aptr = (EPI == 1) ? (const float*)g_AO : A;

    const int tid   = threadIdx.x;
    const int aRow0 = blockIdx.y * GBM;
    const int nCol0 = blockIdx.x * GBN;

    const int tr = (tid >> 4) * 8;   // thread row base within tile
    const int tc = (tid & 15) * 8;   // thread col base within tile

    // loader coords: 64 rows x 4 float4-cols per pass, two passes
    const int lr = tid >> 2;          // 0..63
    const int lc = (tid & 3) * 4;     // 0,4,8,12

    float acc[8][8];
#pragma unroll
    for (int i = 0; i < 8; i++)
#pragma unroll
        for (int j = 0; j < 8; j++) acc[i][j] = 0.0f;

    const int kTiles = K / GBK;
    for (int kt = 0; kt < kTiles; kt++) {
        const int k0 = kt * GBK;
        // load A tile (transposed into As[k][m])
        {
            float4 a0 = *reinterpret_cast<const float4*>(&Aptr[(size_t)(aRow0 + lr) * K + k0 + lc]);
            float4 a1 = *reinterpret_cast<const float4*>(&Aptr[(size_t)(aRow0 + lr + 64) * K + k0 + lc]);
            As[lc + 0][lr] = a0.x; As[lc + 1][lr] = a0.y; As[lc + 2][lr] = a0.z; As[lc + 3][lr] = a0.w;
            As[lc + 0][lr + 64] = a1.x; As[lc + 1][lr + 64] = a1.y; As[lc + 2][lr + 64] = a1.z; As[lc + 3][lr + 64] = a1.w;
        }
        // load W tile (transposed into Bs[k][n])
        {
            float4 b0 = *reinterpret_cast<const float4*>(&W[(size_t)(nCol0 + lr) * K + k0 + lc]);
            float4 b1 = *reinterpret_cast<const float4*>(&W[(size_t)(nCol0 + lr + 64) * K + k0 + lc]);
            Bs[lc + 0][lr] = b0.x; Bs[lc + 1][lr] = b0.y; Bs[lc + 2][lr] = b0.z; Bs[lc + 3][lr] = b0.w;
            Bs[lc + 0][lr + 64] = b1.x; Bs[lc + 1][lr + 64] = b1.y; Bs[lc + 2][lr + 64] = b1.z; Bs[lc + 3][lr + 64] = b1.w;
        }
        __syncthreads();

#pragma unroll
        for (int k = 0; k < GBK; k++) {
            float4 a0 = *reinterpret_cast<const float4*>(&As[k][tr]);
            float4 a1 = *reinterpret_cast<const float4*>(&As[k][tr + 4]);
            float4 b0 = *reinterpret_cast<const float4*>(&Bs[k][tc]);
            float4 b1 = *reinterpret_cast<const float4*>(&Bs[k][tc + 4]);
            float regA[8] = {a0.x, a0.y, a0.z, a0.w, a1.x, a1.y, a1.z, a1.w};
            float regB[8] = {b0.x, b0.y, b0.z, b0.w, b1.x, b1.y, b1.z, b1.w};
#pragma unroll
            for (int i = 0; i < 8; i++)
#pragma unroll
                for (int j = 0; j < 8; j++)
                    acc[i][j] += regA[i] * regB[j];
        }
        __syncthreads();
    }

    if (EPI == 0) {
        // scatter into Q/V/K: n = d*48 + kk*16 + h ; kk: 0->Q, 1->V, 2->K
#pragma unroll
        for (int j = 0; j < 8; j++) {
            const int n  = nCol0 + tc + j;
            const float bj = bias[n];
            const int d  = n / 48;
            const int rem = n - d * 48;
            const int kk = rem >> 4;
            const int hh = rem & 15;
#pragma unroll
            for (int i = 0; i < 8; i++) {
                const int m  = aRow0 + tr + i;
                const int bb = m >> 11;          // m / TSEQ
                const int t  = m & 2047;         // m % TSEQ
                const int idx = (((bb * NH + hh) * TSEQ) + t) * HD + d;
                const float val = acc[i][j] + bj;
                if (kk == 0)      g_Q[idx] = val;
                else if (kk == 1) g_V[idx] = val;
                else              g_K[idx] = val;
            }
        }
    } else {
#pragma unroll
        for (int j = 0; j < 8; j++) {
            const int n = nCol0 + tc + j;
            const float bj = bias[n];
#pragma unroll
            for (int i = 0; i < 8; i++) {
                const int m = aRow0 + tr + i;
                Out[(size_t)m * N + n] = acc[i][j] + bj;
            }
        }
    }
}

// ---------------------------------------------------------------------------
// Causal flash attention, fp32. One thread per query row, 128 rows per CTA,
// 64-key blocks staged in smem. Online softmax with lazy rescale.
// grid = (TSEQ/128, BATCH*NH), block = 128.
// ---------------------------------------------------------------------------
__global__ __launch_bounds__(128)
void flash_kernel()
{
    __shared__ __align__(16) float Ks[64 * HD];
    __shared__ __align__(16) float Vs[64 * HD];

    const int bh   = blockIdx.y;               // b*NH + h
    const int row0 = blockIdx.x * 128;
    const int r    = row0 + threadIdx.x;       // query row (t)

    const float* Qp = g_Q + ((size_t)bh * TSEQ + r) * HD;
    float q[HD];
#pragma unroll
    for (int i = 0; i < HD / 4; i++) {
        float4 v4 = reinterpret_cast<const float4*>(Qp)[i];
        q[4*i+0] = v4.x; q[4*i+1] = v4.y; q[4*i+2] = v4.z; q[4*i+3] = v4.w;
    }

    float o[HD];
#pragma unroll
    for (int i = 0; i < HD; i++) o[i] = 0.0f;
    float mmax = -INFINITY;
    float lsum = 0.0f;

    const float scale = 0.125f;  // 1/sqrt(64)
    const int kEnd = row0 + 128; // last key block (exclusive), causal

    for (int j0 = 0; j0 < kEnd; j0 += 64) {
        // stage K/V block (coalesced)
        const float* Kp = g_K + ((size_t)bh * TSEQ + j0) * HD;
        const float* Vp = g_V + ((size_t)bh * TSEQ + j0) * HD;
#pragma unroll
        for (int it = 0; it < (64 * HD / 4) / 128; it++) {
            int i = it * 128 + threadIdx.x;
            reinterpret_cast<float4*>(Ks)[i] = reinterpret_cast<const float4*>(Kp)[i];
            reinterpret_cast<float4*>(Vs)[i] = reinterpret_cast<const float4*>(Vp)[i];
        }
        __syncthreads();

        int jmax = r - j0 + 1;
        if (jmax > 64) jmax = 64;
        for (int j = 0; j < jmax; j++) {
            // s = q . K[j]
            float s = 0.0f;
            const float4* Kj = reinterpret_cast<const float4*>(Ks + j * HD);
#pragma unroll
            for (int d4 = 0; d4 < HD / 4; d4++) {
                float4 kv = Kj[d4];
                s += q[4*d4+0] * kv.x + q[4*d4+1] * kv.y + q[4*d4+2] * kv.z + q[4*d4+3] * kv.w;
            }
            s *= scale;
            if (s > mmax) {
                float corr = __expf(mmax - s);   // 0 when mmax == -inf
                mmax = s;
                lsum *= corr;
#pragma unroll
                for (int d = 0; d < HD; d++) o[d] *= corr;
            }
            float p = __expf(s - mmax);
            lsum += p;
            const float4* Vj = reinterpret_cast<const float4*>(Vs + j * HD);
#pragma unroll
            for (int d4 = 0; d4 < HD / 4; d4++) {
                float4 vv = Vj[d4];
                o[4*d4+0] += p * vv.x; o[4*d4+1] += p * vv.y;
                o[4*d4+2] += p * vv.z; o[4*d4+3] += p * vv.w;
            }
        }
        __syncthreads();
    }

    const float inv = 1.0f / lsum;
    const int b = bh / NH, h = bh % NH;
    float* Op = g_AO + ((size_t)b * TSEQ + r) * CDIM + h * HD;
#pragma unroll
    for (int i = 0; i < HD / 4; i++) {
        float4 v4;
        v4.x = o[4*i+0] * inv; v4.y = o[4*i+1] * inv;
        v4.z = o[4*i+2] * inv; v4.w = o[4*i+3] * inv;
        reinterpret_cast<float4*>(Op)[i] = v4;
    }
}

// ---------------------------------------------------------------------------
extern "C" void kernel_launch(void* const* d_in, const int* in_sizes, int n_in,
                              void* d_out, int out_size)
{
    const float* x     = (const float*)d_in[0];
    const float* in_w  = (const float*)d_in[1];
    const float* in_b  = (const float*)d_in[2];
    const float* out_w = (const float*)d_in[3];
    const float* out_b = (const float*)d_in[4];
    float* out = (float*)d_out;

    // 1) QKV projection + scatter to (b,h,t,d)
    sgemm_kernel<0><<<dim3(N_QKV / GBN, M_ROWS / GBM), 256>>>(
        x, in_w, in_b, nullptr, M_ROWS, N_QKV, CDIM);

    // 2) causal flash attention
    flash_kernel<<<dim3(TSEQ / 128, BATCH * NH), 128>>>();

    // 3) output projection
    sgemm_kernel<1><<<dim3(CDIM / GBN, M_ROWS / GBM), 256>>>(
        nullptr, out_w, out_b, out, M_ROWS, CDIM, CDIM);
}

// round 9
// speedup vs baseline: 1.3818x; 1.3818x over previous
#include <cuda_runtime.h>
#include <cuda_bf16.h>
#include <math.h>
#include <cstdint>

// Problem constants
#define BATCH 2
#define TSEQ  2048
#define CDIM  1024
#define NH    16
#define HD    64
#define M_ROWS (BATCH*TSEQ)      // 4096
#define N_QKV  (3*CDIM)          // 3072

// Scratch (no cudaMalloc allowed)
__device__ float g_Q[BATCH*NH*TSEQ*HD];
__device__ float g_K[BATCH*NH*TSEQ*HD];
__device__ float g_V[BATCH*NH*TSEQ*HD];
__device__ float g_AO[BATCH*TSEQ*CDIM];

// ---------------------------------------------------------------------------
// bf16 mma: D(16x8,f32) += A(16x16 bf16) * B(8x16 bf16)^T   (row.col)
// ---------------------------------------------------------------------------
__device__ __forceinline__ void mma_bf16(float* c, const uint32_t* a, const uint32_t* b) {
    asm volatile(
        "mma.sync.aligned.m16n8k16.row.col.f32.bf16.bf16.f32 "
        "{%0,%1,%2,%3}, {%4,%5,%6,%7}, {%8,%9}, {%0,%1,%2,%3};"
        : "+f"(c[0]), "+f"(c[1]), "+f"(c[2]), "+f"(c[3])
        : "r"(a[0]), "r"(a[1]), "r"(a[2]), "r"(a[3]), "r"(b[0]), "r"(b[1]));
}

// split two fp32 into packed bf16x2 (hi) and packed bf16x2 (lo residual)
__device__ __forceinline__ void split2(float x, float y, uint32_t& h, uint32_t& l) {
    __nv_bfloat16 hx = __float2bfloat16(x);
    __nv_bfloat16 hy = __float2bfloat16(y);
    float rx = x - __bfloat162float(hx);
    float ry = y - __bfloat162float(hy);
    __nv_bfloat162 hp = __halves2bfloat162(hx, hy);
    __nv_bfloat162 lp = __floats2bfloat162_rn(rx, ry);
    h = *reinterpret_cast<uint32_t*>(&hp);
    l = *reinterpret_cast<uint32_t*>(&lp);
}

// ---------------------------------------------------------------------------
// bf16x3 (Markidis) GEMM: Out[m,n] = sum_k A[m,k]*W[n,k] + bias[n]
// BM=BN=128, BK=32, 256 threads (8 warps, 2x4, 64x32 warp tile).
// Smem tiles: Ahi/Alo/Bhi/Blo, [row][k] bf16, stride 40 bf16 (conflict-free).
// Register-prefetch double buffering.
// EPI=0: scatter into g_Q/g_V/g_K ; EPI=1: A = g_AO, plain store.
// ---------------------------------------------------------------------------
#define TBM 128
#define TBN 128
#define TBK 32
#define SST 40                        // bf16 per smem row (32 + 8 pad)
#define TILE_BF (128*SST)             // 5120 bf16 per tile
#define BUF_BF  (4*TILE_BF)           // Ahi,Alo,Bhi,Blo
#define SMEM_BYTES (2*BUF_BF*2)       // double buffer, bytes = 81920

template<int EPI>
__global__ __launch_bounds__(256)
void gemm_bf16x3(const float* __restrict__ A, const float* __restrict__ W,
                 const float* __restrict__ bias, float* __restrict__ Out,
                 int M, int N, int K)
{
    extern __shared__ __nv_bfloat16 smemb[];
    const float* Aptr = (EPI == 1) ? (const float*)g_AO : A;

    const int tid  = threadIdx.x;
    const int wid  = tid >> 5;
    const int lane = tid & 31;
    const int g    = lane >> 2;      // 0..7
    const int q    = lane & 3;       // 0..3

    const int aRow0 = blockIdx.y * TBM;
    const int nCol0 = blockIdx.x * TBN;
    const int warpM = (wid >> 2) * 64;   // 0 or 64
    const int warpN = (wid & 3) * 32;    // 0,32,64,96

    float acc[4][4][4];
#pragma unroll
    for (int i = 0; i < 4; i++)
#pragma unroll
        for (int j = 0; j < 4; j++)
#pragma unroll
            for (int e = 0; e < 4; e++) acc[i][j][e] = 0.0f;

    const int NC = K / TBK;
    const int lrow = tid >> 3;        // 0..31  (row block of 4 rows? no: see below)
    const int lkq  = tid & 7;         // float4 index along k

    float4 aReg[4], bReg[4];

    auto ldg = [&](int c) {
        const int k0 = c * TBK;
#pragma unroll
        for (int i = 0; i < 4; i++) {
            const int row = lrow + i * 32;
            aReg[i] = *reinterpret_cast<const float4*>(
                &Aptr[(size_t)(aRow0 + row) * K + k0 + lkq * 4]);
            bReg[i] = *reinterpret_cast<const float4*>(
                &W[(size_t)(nCol0 + row) * K + k0 + lkq * 4]);
        }
    };

    auto cvt_sts = [&](int buf) {
        __nv_bfloat16* base = smemb + buf * BUF_BF;
#pragma unroll
        for (int i = 0; i < 4; i++) {
            const int row = lrow + i * 32;
            const int u32i = row * (SST / 2) + lkq * 2;   // uint32 index in tile
            uint2 h, l;
            split2(aReg[i].x, aReg[i].y, h.x, l.x);
            split2(aReg[i].z, aReg[i].w, h.y, l.y);
            *reinterpret_cast<uint2*>(reinterpret_cast<uint32_t*>(base) + u32i) = h;
            *reinterpret_cast<uint2*>(reinterpret_cast<uint32_t*>(base + TILE_BF) + u32i) = l;
            split2(bReg[i].x, bReg[i].y, h.x, l.x);
            split2(bReg[i].z, bReg[i].w, h.y, l.y);
            *reinterpret_cast<uint2*>(reinterpret_cast<uint32_t*>(base + 2*TILE_BF) + u32i) = h;
            *reinterpret_cast<uint2*>(reinterpret_cast<uint32_t*>(base + 3*TILE_BF) + u32i) = l;
        }
    };

    // prologue: stage chunk 0
    ldg(0);
    cvt_sts(0);

    for (int c = 0; c < NC; c++) {
        const int buf = c & 1;
        if (c + 1 < NC) ldg(c + 1);
        __syncthreads();

        const uint32_t* Ah = reinterpret_cast<const uint32_t*>(smemb + buf * BUF_BF);
        const uint32_t* Al = Ah + TILE_BF / 2;
        const uint32_t* Bh = Ah + TILE_BF;          // 2*TILE_BF bf16 = TILE_BF uint32
        const uint32_t* Bl = Ah + 3 * TILE_BF / 2;

#pragma unroll
        for (int ks = 0; ks < 2; ks++) {
            const int kb2 = ks * 8;                  // k offset in uint32 units (16 bf16)
            uint32_t ah[4][4], al[4][4], bh[4][2], bl[4][2];
#pragma unroll
            for (int i = 0; i < 4; i++) {
                const int r0 = (warpM + i * 16 + g) * (SST / 2) + kb2 + q;
                const int r1 = r0 + 8 * (SST / 2);
                ah[i][0] = Ah[r0];     ah[i][1] = Ah[r1];
                ah[i][2] = Ah[r0 + 4]; ah[i][3] = Ah[r1 + 4];
                al[i][0] = Al[r0];     al[i][1] = Al[r1];
                al[i][2] = Al[r0 + 4]; al[i][3] = Al[r1 + 4];
            }
#pragma unroll
            for (int j = 0; j < 4; j++) {
                const int r = (warpN + j * 8 + g) * (SST / 2) + kb2 + q;
                bh[j][0] = Bh[r]; bh[j][1] = Bh[r + 4];
                bl[j][0] = Bl[r]; bl[j][1] = Bl[r + 4];
            }
#pragma unroll
            for (int i = 0; i < 4; i++)
#pragma unroll
                for (int j = 0; j < 4; j++) {
                    mma_bf16(acc[i][j], ah[i], bh[j]);
                    mma_bf16(acc[i][j], al[i], bh[j]);
                    mma_bf16(acc[i][j], ah[i], bl[j]);
                }
        }
        if (c + 1 < NC) cvt_sts((c + 1) & 1);
    }

    // ---------------- epilogue ----------------
#pragma unroll
    for (int i = 0; i < 4; i++) {
        const int mlo = aRow0 + warpM + i * 16 + g;
        const int mhi = mlo + 8;
#pragma unroll
        for (int j = 0; j < 4; j++) {
            const int n0 = nCol0 + warpN + j * 8 + 2 * q;
            const float b0 = __ldg(&bias[n0]);
            const float b1 = __ldg(&bias[n0 + 1]);
            float v00 = acc[i][j][0] + b0;
            float v01 = acc[i][j][1] + b1;
            float v10 = acc[i][j][2] + b0;
            float v11 = acc[i][j][3] + b1;
            if (EPI == 0) {
                // scatter: n = d*48 + kk*16 + h ; kk: 0->Q, 1->V, 2->K
#pragma unroll
                for (int e = 0; e < 4; e++) {
                    const int n = n0 + (e & 1);
                    const int m = (e < 2) ? mlo : mhi;
                    const float val = (e == 0) ? v00 : (e == 1) ? v01 : (e == 2) ? v10 : v11;
                    const int d   = n / 48;
                    const int rem = n - d * 48;
                    const int kk  = rem >> 4;
                    const int hh  = rem & 15;
                    const int bb  = m >> 11, t = m & 2047;
                    const int idx = (((bb * NH + hh) * TSEQ) + t) * HD + d;
                    if (kk == 0)      g_Q[idx] = val;
                    else if (kk == 1) g_V[idx] = val;
                    else              g_K[idx] = val;
                }
            } else {
                *reinterpret_cast<float2*>(&Out[(size_t)mlo * N + n0]) = make_float2(v00, v01);
                *reinterpret_cast<float2*>(&Out[(size_t)mhi * N + n0]) = make_float2(v10, v11);
            }
        }
    }
}

// ---------------------------------------------------------------------------
// Causal flash attention, fp32 (unchanged; target of next round)
// ---------------------------------------------------------------------------
__global__ __launch_bounds__(128)
void flash_kernel()
{
    __shared__ __align__(16) float Ks[64 * HD];
    __shared__ __align__(16) float Vs[64 * HD];

    const int bh   = blockIdx.y;
    const int row0 = blockIdx.x * 128;
    const int r    = row0 + threadIdx.x;

    const float* Qp = g_Q + ((size_t)bh * TSEQ + r) * HD;
    float q[HD];
#pragma unroll
    for (int i = 0; i < HD / 4; i++) {
        float4 v4 = reinterpret_cast<const float4*>(Qp)[i];
        q[4*i+0] = v4.x; q[4*i+1] = v4.y; q[4*i+2] = v4.z; q[4*i+3] = v4.w;
    }

    float o[HD];
#pragma unroll
    for (int i = 0; i < HD; i++) o[i] = 0.0f;
    float mmax = -INFINITY;
    float lsum = 0.0f;

    const float scale = 0.125f;
    const int kEnd = row0 + 128;

    for (int j0 = 0; j0 < kEnd; j0 += 64) {
        const float* Kp = g_K + ((size_t)bh * TSEQ + j0) * HD;
        const float* Vp = g_V + ((size_t)bh * TSEQ + j0) * HD;
#pragma unroll
        for (int it = 0; it < (64 * HD / 4) / 128; it++) {
            int i = it * 128 + threadIdx.x;
            reinterpret_cast<float4*>(Ks)[i] = reinterpret_cast<const float4*>(Kp)[i];
            reinterpret_cast<float4*>(Vs)[i] = reinterpret_cast<const float4*>(Vp)[i];
        }
        __syncthreads();

        int jmax = r - j0 + 1;
        if (jmax > 64) jmax = 64;
        for (int j = 0; j < jmax; j++) {
            float s = 0.0f;
            const float4* Kj = reinterpret_cast<const float4*>(Ks + j * HD);
#pragma unroll
            for (int d4 = 0; d4 < HD / 4; d4++) {
                float4 kv = Kj[d4];
                s += q[4*d4+0] * kv.x + q[4*d4+1] * kv.y + q[4*d4+2] * kv.z + q[4*d4+3] * kv.w;
            }
            s *= scale;
            if (s > mmax) {
                float corr = __expf(mmax - s);
                mmax = s;
                lsum *= corr;
#pragma unroll
                for (int d = 0; d < HD; d++) o[d] *= corr;
            }
            float p = __expf(s - mmax);
            lsum += p;
            const float4* Vj = reinterpret_cast<const float4*>(Vs + j * HD);
#pragma unroll
            for (int d4 = 0; d4 < HD / 4; d4++) {
                float4 vv = Vj[d4];
                o[4*d4+0] += p * vv.x; o[4*d4+1] += p * vv.y;
                o[4*d4+2] += p * vv.z; o[4*d4+3] += p * vv.w;
            }
        }
        __syncthreads();
    }

    const float inv = 1.0f / lsum;
    const int b = bh / NH, h = bh % NH;
    float* Op = g_AO + ((size_t)b * TSEQ + r) * CDIM + h * HD;
#pragma unroll
    for (int i = 0; i < HD / 4; i++) {
        float4 v4;
        v4.x = o[4*i+0] * inv; v4.y = o[4*i+1] * inv;
        v4.z = o[4*i+2] * inv; v4.w = o[4*i+3] * inv;
        reinterpret_cast<float4*>(Op)[i] = v4;
    }
}

// ---------------------------------------------------------------------------
extern "C" void kernel_launch(void* const* d_in, const int* in_sizes, int n_in,
                              void* d_out, int out_size)
{
    const float* x     = (const float*)d_in[0];
    const float* in_w  = (const float*)d_in[1];
    const float* in_b  = (const float*)d_in[2];
    const float* out_w = (const float*)d_in[3];
    const float* out_b = (const float*)d_in[4];
    float* out = (float*)d_out;

    cudaFuncSetAttribute(gemm_bf16x3<0>, cudaFuncAttributeMaxDynamicSharedMemorySize, SMEM_BYTES);
    cudaFuncSetAttribute(gemm_bf16x3<1>, cudaFuncAttributeMaxDynamicSharedMemorySize, SMEM_BYTES);

    // 1) QKV projection (bf16x3 tensor cores) + scatter to (b,h,t,d)
    gemm_bf16x3<0><<<dim3(N_QKV / TBN, M_ROWS / TBM), 256, SMEM_BYTES>>>(
        x, in_w, in_b, nullptr, M_ROWS, N_QKV, CDIM);

    // 2) causal flash attention (fp32)
    flash_kernel<<<dim3(TSEQ / 128, BATCH * NH), 128>>>();

    // 3) output projection (bf16x3 tensor cores)
    gemm_bf16x3<1><<<dim3(CDIM / TBN, M_ROWS / TBM), 256, SMEM_BYTES>>>(
        nullptr, out_w, out_b, out, M_ROWS, CDIM, CDIM);
}

// round 12
// speedup vs baseline: 2.2902x; 1.6575x over previous
#include <cuda_runtime.h>
#include <cuda_bf16.h>
#include <math.h>
#include <cstdint>

// Problem constants
#define BATCH 2
#define TSEQ  2048
#define CDIM  1024
#define NH    16
#define HD    64
#define M_ROWS (BATCH*TSEQ)      // 4096
#define N_QKV  (3*CDIM)          // 3072

// Scratch (no cudaMalloc allowed)
__device__ float g_Q[BATCH*NH*TSEQ*HD];
__device__ float g_K[BATCH*NH*TSEQ*HD];
__device__ float g_V[BATCH*NH*TSEQ*HD];
__device__ float g_AO[BATCH*TSEQ*CDIM];

// ---------------------------------------------------------------------------
// bf16 mma: D(16x8,f32) += A(16x16 bf16) * B(8x16 bf16)^T   (row.col)
// ---------------------------------------------------------------------------
__device__ __forceinline__ void mma_bf16(float* c, const uint32_t* a, const uint32_t* b) {
    asm volatile(
        "mma.sync.aligned.m16n8k16.row.col.f32.bf16.bf16.f32 "
        "{%0,%1,%2,%3}, {%4,%5,%6,%7}, {%8,%9}, {%0,%1,%2,%3};"
        : "+f"(c[0]), "+f"(c[1]), "+f"(c[2]), "+f"(c[3])
        : "r"(a[0]), "r"(a[1]), "r"(a[2]), "r"(a[3]), "r"(b[0]), "r"(b[1]));
}

// split two fp32 into packed bf16x2 (hi) and packed bf16x2 (lo residual)
__device__ __forceinline__ void split2(float x, float y, uint32_t& h, uint32_t& l) {
    __nv_bfloat16 hx = __float2bfloat16(x);
    __nv_bfloat16 hy = __float2bfloat16(y);
    float rx = x - __bfloat162float(hx);
    float ry = y - __bfloat162float(hy);
    __nv_bfloat162 hp = __halves2bfloat162(hx, hy);
    __nv_bfloat162 lp = __floats2bfloat162_rn(rx, ry);
    h = *reinterpret_cast<uint32_t*>(&hp);
    l = *reinterpret_cast<uint32_t*>(&lp);
}

// fast exp for x <= 0 (handles very negative / -1e30 -> ~0). FMA pipe only.
__device__ __forceinline__ float fast_exp(float x) {
    x = fmaxf(x, -87.0f);
    const float LOG2E = 1.4426950408889634f;
    float t  = fmaf(x, LOG2E, 12582912.0f);          // round(y) in mantissa
    int   ni = __float_as_int(t) - 0x4B400000;       // integer part
    float f  = fmaf(x, LOG2E, -(t - 12582912.0f));   // frac in [-0.5,0.5]
    float p = 0.0013333558146428443f;
    p = fmaf(p, f, 0.009618129107628477f);
    p = fmaf(p, f, 0.05550410866482158f);
    p = fmaf(p, f, 0.2402265069591007f);
    p = fmaf(p, f, 0.6931471805599453f);
    p = fmaf(p, f, 1.0f);
    return p * __int_as_float((ni + 127) << 23);
}

// ---------------------------------------------------------------------------
// bf16x3 (Markidis) GEMM (unchanged from round 9)
// ---------------------------------------------------------------------------
#define TBM 128
#define TBN 128
#define TBK 32
#define SST 40
#define TILE_BF (128*SST)
#define BUF_BF  (4*TILE_BF)
#define SMEM_BYTES (2*BUF_BF*2)

template<int EPI>
__global__ __launch_bounds__(256)
void gemm_bf16x3(const float* __restrict__ A, const float* __restrict__ W,
                 const float* __restrict__ bias, float* __restrict__ Out,
                 int M, int N, int K)
{
    extern __shared__ __nv_bfloat16 smemb[];
    const float* Aptr = (EPI == 1) ? (const float*)g_AO : A;

    const int tid  = threadIdx.x;
    const int wid  = tid >> 5;
    const int lane = tid & 31;
    const int g    = lane >> 2;
    const int q    = lane & 3;

    const int aRow0 = blockIdx.y * TBM;
    const int nCol0 = blockIdx.x * TBN;
    const int warpM = (wid >> 2) * 64;
    const int warpN = (wid & 3) * 32;

    float acc[4][4][4];
#pragma unroll
    for (int i = 0; i < 4; i++)
#pragma unroll
        for (int j = 0; j < 4; j++)
#pragma unroll
            for (int e = 0; e < 4; e++) acc[i][j][e] = 0.0f;

    const int NC = K / TBK;
    const int lrow = tid >> 3;
    const int lkq  = tid & 7;

    float4 aReg[4], bReg[4];

    auto ldg = [&](int c) {
        const int k0 = c * TBK;
#pragma unroll
        for (int i = 0; i < 4; i++) {
            const int row = lrow + i * 32;
            aReg[i] = *reinterpret_cast<const float4*>(
                &Aptr[(size_t)(aRow0 + row) * K + k0 + lkq * 4]);
            bReg[i] = *reinterpret_cast<const float4*>(
                &W[(size_t)(nCol0 + row) * K + k0 + lkq * 4]);
        }
    };

    auto cvt_sts = [&](int buf) {
        __nv_bfloat16* base = smemb + buf * BUF_BF;
#pragma unroll
        for (int i = 0; i < 4; i++) {
            const int row = lrow + i * 32;
            const int u32i = row * (SST / 2) + lkq * 2;
            uint2 h, l;
            split2(aReg[i].x, aReg[i].y, h.x, l.x);
            split2(aReg[i].z, aReg[i].w, h.y, l.y);
            *reinterpret_cast<uint2*>(reinterpret_cast<uint32_t*>(base) + u32i) = h;
            *reinterpret_cast<uint2*>(reinterpret_cast<uint32_t*>(base + TILE_BF) + u32i) = l;
            split2(bReg[i].x, bReg[i].y, h.x, l.x);
            split2(bReg[i].z, bReg[i].w, h.y, l.y);
            *reinterpret_cast<uint2*>(reinterpret_cast<uint32_t*>(base + 2*TILE_BF) + u32i) = h;
            *reinterpret_cast<uint2*>(reinterpret_cast<uint32_t*>(base + 3*TILE_BF) + u32i) = l;
        }
    };

    ldg(0);
    cvt_sts(0);

    for (int c = 0; c < NC; c++) {
        const int buf = c & 1;
        if (c + 1 < NC) ldg(c + 1);
        __syncthreads();

        const uint32_t* Ah = reinterpret_cast<const uint32_t*>(smemb + buf * BUF_BF);
        const uint32_t* Al = Ah + TILE_BF / 2;
        const uint32_t* Bh = Ah + TILE_BF;
        const uint32_t* Bl = Ah + 3 * TILE_BF / 2;

#pragma unroll
        for (int ks = 0; ks < 2; ks++) {
            const int kb2 = ks * 8;
            uint32_t ah[4][4], al[4][4], bh[4][2], bl[4][2];
#pragma unroll
            for (int i = 0; i < 4; i++) {
                const int r0 = (warpM + i * 16 + g) * (SST / 2) + kb2 + q;
                const int r1 = r0 + 8 * (SST / 2);
                ah[i][0] = Ah[r0];     ah[i][1] = Ah[r1];
                ah[i][2] = Ah[r0 + 4]; ah[i][3] = Ah[r1 + 4];
                al[i][0] = Al[r0];     al[i][1] = Al[r1];
                al[i][2] = Al[r0 + 4]; al[i][3] = Al[r1 + 4];
            }
#pragma unroll
            for (int j = 0; j < 4; j++) {
                const int r = (warpN + j * 8 + g) * (SST / 2) + kb2 + q;
                bh[j][0] = Bh[r]; bh[j][1] = Bh[r + 4];
                bl[j][0] = Bl[r]; bl[j][1] = Bl[r + 4];
            }
#pragma unroll
            for (int i = 0; i < 4; i++)
#pragma unroll
                for (int j = 0; j < 4; j++) {
                    mma_bf16(acc[i][j], ah[i], bh[j]);
                    mma_bf16(acc[i][j], al[i], bh[j]);
                    mma_bf16(acc[i][j], ah[i], bl[j]);
                }
        }
        if (c + 1 < NC) cvt_sts((c + 1) & 1);
    }

#pragma unroll
    for (int i = 0; i < 4; i++) {
        const int mlo = aRow0 + warpM + i * 16 + g;
        const int mhi = mlo + 8;
#pragma unroll
        for (int j = 0; j < 4; j++) {
            const int n0 = nCol0 + warpN + j * 8 + 2 * q;
            const float b0 = __ldg(&bias[n0]);
            const float b1 = __ldg(&bias[n0 + 1]);
            float v00 = acc[i][j][0] + b0;
            float v01 = acc[i][j][1] + b1;
            float v10 = acc[i][j][2] + b0;
            float v11 = acc[i][j][3] + b1;
            if (EPI == 0) {
#pragma unroll
                for (int e = 0; e < 4; e++) {
                    const int n = n0 + (e & 1);
                    const int m = (e < 2) ? mlo : mhi;
                    const float val = (e == 0) ? v00 : (e == 1) ? v01 : (e == 2) ? v10 : v11;
                    const int d   = n / 48;
                    const int rem = n - d * 48;
                    const int kk  = rem >> 4;
                    const int hh  = rem & 15;
                    const int bb  = m >> 11, t = m & 2047;
                    const int idx = (((bb * NH + hh) * TSEQ) + t) * HD + d;
                    if (kk == 0)      g_Q[idx] = val;
                    else if (kk == 1) g_V[idx] = val;
                    else              g_K[idx] = val;
                }
            } else {
                *reinterpret_cast<float2*>(&Out[(size_t)mlo * N + n0]) = make_float2(v00, v01);
                *reinterpret_cast<float2*>(&Out[(size_t)mhi * N + n0]) = make_float2(v10, v11);
            }
        }
    }
}

// ---------------------------------------------------------------------------
// Tensor-core causal flash attention (bf16x3 split, poly exp).
// 128 q-rows/CTA, 64-key blocks, 8 warps (16 rows each), 256 threads.
// S = Q K^T via split mma; P fragments reused in registers for P V^T mma.
// grid = (TSEQ/128, BATCH*NH)
// ---------------------------------------------------------------------------
#define FKS 36            // uint32 stride per smem row (64 bf16 + 8 pad)

__global__ __launch_bounds__(256)
void flash_tc()
{
    __shared__ uint32_t sKhi[64*FKS], sKlo[64*FKS];
    __shared__ __nv_bfloat16 sVthi[64*(2*FKS)], sVtlo[64*(2*FKS)];

    const int tid  = threadIdx.x;
    const int wid  = tid >> 5;
    const int lane = tid & 31;
    const int g    = lane >> 2;
    const int q    = lane & 3;

    const int bh   = blockIdx.y;
    const int row0 = blockIdx.x * 128;
    const int r0   = row0 + wid * 16 + g;   // this thread's first row
    const int r1   = r0 + 8;

    // Q fragments (scaled by 1/sqrt(D)), split hi/lo. a-layout of m16n8k16.
    uint32_t qh[4][4], ql[4][4];
    {
        const float* Qb = g_Q + ((size_t)bh * TSEQ) * HD;
        const float sc = 0.125f;
#pragma unroll
        for (int kc = 0; kc < 4; kc++) {
            const int d0 = kc * 16 + 2 * q;
            float2 x0 = *reinterpret_cast<const float2*>(Qb + (size_t)r0 * HD + d0);
            float2 x1 = *reinterpret_cast<const float2*>(Qb + (size_t)r1 * HD + d0);
            float2 x2 = *reinterpret_cast<const float2*>(Qb + (size_t)r0 * HD + d0 + 8);
            float2 x3 = *reinterpret_cast<const float2*>(Qb + (size_t)r1 * HD + d0 + 8);
            split2(x0.x * sc, x0.y * sc, qh[kc][0], ql[kc][0]);
            split2(x1.x * sc, x1.y * sc, qh[kc][1], ql[kc][1]);
            split2(x2.x * sc, x2.y * sc, qh[kc][2], ql[kc][2]);
            split2(x3.x * sc, x3.y * sc, qh[kc][3], ql[kc][3]);
        }
    }

    float o[8][4];
#pragma unroll
    for (int n = 0; n < 8; n++)
#pragma unroll
        for (int e = 0; e < 4; e++) o[n][e] = 0.0f;
    float m0 = -INFINITY, m1 = -INFINITY, l0 = 0.0f, l1 = 0.0f;

    const int srow = tid >> 2;          // 0..63
    const int sseg = tid & 3;           // 0..3
    const uint32_t* Vthi_u = reinterpret_cast<const uint32_t*>(sVthi);
    const uint32_t* Vtlo_u = reinterpret_cast<const uint32_t*>(sVtlo);

    for (int j0 = 0; j0 < row0 + 128; j0 += 64) {
        __syncthreads();   // previous block's smem reads done
        // ---- stage K (row-major) and V (transposed) as split bf16 ----
        {
            const float* Kg = g_K + ((size_t)bh * TSEQ + j0 + srow) * HD + sseg * 16;
            const float* Vg = g_V + ((size_t)bh * TSEQ + j0 + srow) * HD + sseg * 16;
#pragma unroll
            for (int i = 0; i < 4; i++) {
                float4 kv = *reinterpret_cast<const float4*>(Kg + i * 4);
                uint32_t h0, lo0, h1, lo1;
                split2(kv.x, kv.y, h0, lo0);
                split2(kv.z, kv.w, h1, lo1);
                const int u = srow * FKS + sseg * 8 + i * 2;
                sKhi[u] = h0; sKhi[u + 1] = h1;
                sKlo[u] = lo0; sKlo[u + 1] = lo1;

                float4 vv = *reinterpret_cast<const float4*>(Vg + i * 4);
                const int c = sseg * 16 + i * 4;
#pragma unroll
                for (int e = 0; e < 4; e++) {
                    float f = (e == 0) ? vv.x : (e == 1) ? vv.y : (e == 2) ? vv.z : vv.w;
                    __nv_bfloat16 hb = __float2bfloat16(f);
                    __nv_bfloat16 lb = __float2bfloat16(f - __bfloat162float(hb));
                    sVthi[(c + e) * (2*FKS) + srow] = hb;
                    sVtlo[(c + e) * (2*FKS) + srow] = lb;
                }
            }
        }
        __syncthreads();

        // warps whose rows are entirely above the diagonal skip compute
        if (j0 > row0 + wid * 16 + 15) continue;

        // ---- S = Q K^T ----
        float s[8][4];
#pragma unroll
        for (int n = 0; n < 8; n++)
#pragma unroll
            for (int e = 0; e < 4; e++) s[n][e] = 0.0f;

#pragma unroll
        for (int kc = 0; kc < 4; kc++) {
#pragma unroll
            for (int n = 0; n < 8; n++) {
                const int r = (8 * n + g) * FKS + kc * 8 + q;
                uint32_t bhf[2] = { sKhi[r], sKhi[r + 4] };
                uint32_t blf[2] = { sKlo[r], sKlo[r + 4] };
                mma_bf16(s[n], qh[kc], bhf);
                mma_bf16(s[n], ql[kc], bhf);
                mma_bf16(s[n], qh[kc], blf);
            }
        }

        // ---- causal mask (only near the diagonal) ----
        if (j0 + 63 > row0 + wid * 16) {
#pragma unroll
            for (int n = 0; n < 8; n++) {
                const int col = j0 + 8 * n + 2 * q;
                if (col > r0)     s[n][0] = -1e30f;
                if (col + 1 > r0) s[n][1] = -1e30f;
                if (col > r1)     s[n][2] = -1e30f;
                if (col + 1 > r1) s[n][3] = -1e30f;
            }
        }

        // ---- online softmax ----
        float rmax0 = -1e30f, rmax1 = -1e30f;
#pragma unroll
        for (int n = 0; n < 8; n++) {
            rmax0 = fmaxf(rmax0, fmaxf(s[n][0], s[n][1]));
            rmax1 = fmaxf(rmax1, fmaxf(s[n][2], s[n][3]));
        }
        rmax0 = fmaxf(rmax0, __shfl_xor_sync(0xFFFFFFFFu, rmax0, 1));
        rmax0 = fmaxf(rmax0, __shfl_xor_sync(0xFFFFFFFFu, rmax0, 2));
        rmax1 = fmaxf(rmax1, __shfl_xor_sync(0xFFFFFFFFu, rmax1, 1));
        rmax1 = fmaxf(rmax1, __shfl_xor_sync(0xFFFFFFFFu, rmax1, 2));

        const float mn0 = fmaxf(m0, rmax0);
        const float mn1 = fmaxf(m1, rmax1);
        const float sc0 = fast_exp(m0 - mn0);
        const float sc1 = fast_exp(m1 - mn1);
        m0 = mn0; m1 = mn1;

        float p[8][4];
        float sum0 = 0.0f, sum1 = 0.0f;
#pragma unroll
        for (int n = 0; n < 8; n++) {
            p[n][0] = fast_exp(s[n][0] - mn0);
            p[n][1] = fast_exp(s[n][1] - mn0);
            p[n][2] = fast_exp(s[n][2] - mn1);
            p[n][3] = fast_exp(s[n][3] - mn1);
            sum0 += p[n][0] + p[n][1];
            sum1 += p[n][2] + p[n][3];
        }
        sum0 += __shfl_xor_sync(0xFFFFFFFFu, sum0, 1);
        sum0 += __shfl_xor_sync(0xFFFFFFFFu, sum0, 2);
        sum1 += __shfl_xor_sync(0xFFFFFFFFu, sum1, 1);
        sum1 += __shfl_xor_sync(0xFFFFFFFFu, sum1, 2);
        l0 = l0 * sc0 + sum0;
        l1 = l1 * sc1 + sum1;

#pragma unroll
        for (int n = 0; n < 8; n++) {
            o[n][0] *= sc0; o[n][1] *= sc0;
            o[n][2] *= sc1; o[n][3] *= sc1;
        }

        // ---- O += P V  (P fragments built in registers, split hi/lo) ----
#pragma unroll
        for (int t = 0; t < 4; t++) {
            uint32_t ah[4], al[4];
            split2(p[2*t][0],     p[2*t][1],     ah[0], al[0]);
            split2(p[2*t][2],     p[2*t][3],     ah[1], al[1]);
            split2(p[2*t + 1][0], p[2*t + 1][1], ah[2], al[2]);
            split2(p[2*t + 1][2], p[2*t + 1][3], ah[3], al[3]);
#pragma unroll
            for (int n = 0; n < 8; n++) {
                const int r = (8 * n + g) * FKS + t * 8 + q;
                uint32_t vh[2] = { Vthi_u[r], Vthi_u[r + 4] };
                uint32_t vl[2] = { Vtlo_u[r], Vtlo_u[r + 4] };
                mma_bf16(o[n], ah, vh);
                mma_bf16(o[n], al, vh);
                mma_bf16(o[n], ah, vl);
            }
        }
    }

    // ---- write O / l ----
    const float inv0 = 1.0f / l0;
    const float inv1 = 1.0f / l1;
    const int b = bh >> 4, h = bh & 15;
    float* O0 = g_AO + ((size_t)b * TSEQ + r0) * CDIM + h * HD;
    float* O1 = g_AO + ((size_t)b * TSEQ + r1) * CDIM + h * HD;
#pragma unroll
    for (int n = 0; n < 8; n++) {
        *reinterpret_cast<float2*>(O0 + 8 * n + 2 * q) =
            make_float2(o[n][0] * inv0, o[n][1] * inv0);
        *reinterpret_cast<float2*>(O1 + 8 * n + 2 * q) =
            make_float2(o[n][2] * inv1, o[n][3] * inv1);
    }
}

// ---------------------------------------------------------------------------
extern "C" void kernel_launch(void* const* d_in, const int* in_sizes, int n_in,
                              void* d_out, int out_size)
{
    const float* x     = (const float*)d_in[0];
    const float* in_w  = (const float*)d_in[1];
    const float* in_b  = (const float*)d_in[2];
    const float* out_w = (const float*)d_in[3];
    const float* out_b = (const float*)d_in[4];
    float* out = (float*)d_out;

    cudaFuncSetAttribute(gemm_bf16x3<0>, cudaFuncAttributeMaxDynamicSharedMemorySize, SMEM_BYTES);
    cudaFuncSetAttribute(gemm_bf16x3<1>, cudaFuncAttributeMaxDynamicSharedMemorySize, SMEM_BYTES);

    // 1) QKV projection (bf16x3 tensor cores) + scatter to (b,h,t,d)
    gemm_bf16x3<0><<<dim3(N_QKV / TBN, M_ROWS / TBM), 256, SMEM_BYTES>>>(
        x, in_w, in_b, nullptr, M_ROWS, N_QKV, CDIM);

    // 2) causal flash attention (bf16x3 tensor cores)
    flash_tc<<<dim3(TSEQ / 128, BATCH * NH), 256>>>();

    // 3) output projection (bf16x3 tensor cores)
    gemm_bf16x3<1><<<dim3(CDIM / TBN, M_ROWS / TBM), 256, SMEM_BYTES>>>(
        nullptr, out_w, out_b, out, M_ROWS, CDIM, CDIM);
}